// round 1
// baseline (speedup 1.0000x reference)
#include <cuda_runtime.h>
#include <math.h>

#define N_TOK 1024
#define DIMV  512
#define HEADS 8
#define DH    64
#define JTOT  1026          // NULL_KV(2) + N_TOK
#define JPAD  1088          // 17 * 64
#define INV_EPS 10.0f
#define EPSF    0.1f
#define LOGK    2.0794415416798357f   // log(8)
#define CD_ITERS 50

// ---------------- scratch (no allocations allowed) ----------------
__device__ float g_xn[N_TOK * DIMV];
__device__ float g_q [HEADS * N_TOK * DH];
__device__ float g_k [HEADS * JPAD * DH];
__device__ float g_v [HEADS * JPAD * DH];
__device__ float g_s [HEADS * N_TOK * JPAD];   // scores, later overwritten with probs
__device__ float g_o [N_TOK * DIMV];           // attention output (n, h*dh)

// ---------------- block reductions (256 threads, 8 warps) ----------------
__device__ __forceinline__ float block_max_256(float v, float* red) {
#pragma unroll
    for (int o = 16; o; o >>= 1) v = fmaxf(v, __shfl_xor_sync(0xffffffffu, v, o));
    __syncthreads();                       // protect red from previous use
    if ((threadIdx.x & 31) == 0) red[threadIdx.x >> 5] = v;
    __syncthreads();
    v = red[threadIdx.x & 7];
#pragma unroll
    for (int o = 4; o; o >>= 1) v = fmaxf(v, __shfl_xor_sync(0xffffffffu, v, o));
    return v;
}

__device__ __forceinline__ float block_sum_256(float v, float* red) {
#pragma unroll
    for (int o = 16; o; o >>= 1) v += __shfl_xor_sync(0xffffffffu, v, o);
    __syncthreads();
    if ((threadIdx.x & 31) == 0) red[threadIdx.x >> 5] = v;
    __syncthreads();
    v = red[threadIdx.x & 7];
#pragma unroll
    for (int o = 4; o; o >>= 1) v += __shfl_xor_sync(0xffffffffu, v, o);
    return v;
}

// ---------------- LayerNorm: one block per row, 256 thr, 2 elem each ----------------
__global__ void ln_kernel(const float* __restrict__ x, const float* __restrict__ gam,
                          const float* __restrict__ bet) {
    __shared__ float red[8];
    const int row = blockIdx.x;
    const int tid = threadIdx.x;
    const float v0 = x[row * DIMV + tid];
    const float v1 = x[row * DIMV + tid + 256];
    float s  = v0 + v1;
    float sq = v0 * v0 + v1 * v1;
    s  = block_sum_256(s,  red);
    sq = block_sum_256(sq, red);
    const float mean = s * (1.0f / 512.0f);
    const float var  = sq * (1.0f / 512.0f) - mean * mean;
    const float rstd = rsqrtf(var + 1e-5f);
    g_xn[row * DIMV + tid]       = (v0 - mean) * rstd * gam[tid]       + bet[tid];
    g_xn[row * DIMV + tid + 256] = (v1 - mean) * rstd * gam[tid + 256] + bet[tid + 256];
}

// ---------------- fill null kv rows (j=0,1) and zero pad rows (j=1026..1087) ----------
__global__ void fill_kernel(const float* __restrict__ null_kv) {
    const int idx = blockIdx.x * blockDim.x + threadIdx.x;   // 64*512 = 32768
    const int h = idx >> 12;          // 4096 per head
    const int r = (idx >> 6) & 63;
    const int d = idx & 63;
    if (r < 2) {
        g_k[(h * JPAD + r) * DH + d] = null_kv[((0 * HEADS + h) * 2 + r) * DH + d];
        g_v[(h * JPAD + r) * DH + d] = null_kv[((1 * HEADS + h) * 2 + r) * DH + d];
    } else {
        const int j = 1024 + r;       // 1026..1087
        g_k[(h * JPAD + j) * DH + d] = 0.0f;
        g_v[(h * JPAD + j) * DH + d] = 0.0f;
    }
}

// ---------------- generic 64x64 tiled GEMM, M=1024, K=512 -----------------------------
// qkv_mode=1: A=g_xn, B=w_qkv (ldb=1536), scatter into g_q (scaled) / g_k / g_v
// qkv_mode=0: A=g_o,  B=w_out (ldb=512),  plain store into C
__global__ void gemm_kernel(const float* __restrict__ B, float* __restrict__ C,
                            int ldb, int qkv_mode) {
    __shared__ float As[16][64];
    __shared__ float Bs[16][64];
    const float* __restrict__ A = qkv_mode ? g_xn : g_o;
    const int bx = blockIdx.x, by = blockIdx.y, tid = threadIdx.x;
    const int tx = tid & 15, ty = tid >> 4;
    const int ar = tid >> 2, ac = (tid & 3) << 2;    // A tile: 64 rows x 16 k
    const int br = tid >> 4, bc = (tid & 15) << 2;   // B tile: 16 k x 64 cols
    float acc[4][4] = {};
    for (int k0 = 0; k0 < 512; k0 += 16) {
        float4 a4 = *(const float4*)(A + (by * 64 + ar) * 512 + k0 + ac);
        As[ac + 0][ar] = a4.x; As[ac + 1][ar] = a4.y;
        As[ac + 2][ar] = a4.z; As[ac + 3][ar] = a4.w;
        float4 b4 = *(const float4*)(B + (size_t)(k0 + br) * ldb + bx * 64 + bc);
        *(float4*)&Bs[br][bc] = b4;
        __syncthreads();
#pragma unroll
        for (int kk = 0; kk < 16; kk++) {
            float ra[4], rb[4];
            *(float4*)ra = *(const float4*)&As[kk][ty << 2];
            *(float4*)rb = *(const float4*)&Bs[kk][tx << 2];
#pragma unroll
            for (int ii = 0; ii < 4; ii++)
#pragma unroll
                for (int jj = 0; jj < 4; jj++)
                    acc[ii][jj] += ra[ii] * rb[jj];
        }
        __syncthreads();
    }
#pragma unroll
    for (int ii = 0; ii < 4; ii++) {
        const int row = by * 64 + (ty << 2) + ii;
#pragma unroll
        for (int jj = 0; jj < 4; jj++) {
            const int col = bx * 64 + (tx << 2) + jj;
            const float val = acc[ii][jj];
            if (qkv_mode) {
                const int h = (col >> 6) & 7, d = col & 63, w = col >> 9;
                if (w == 0)      g_q[(h * N_TOK + row) * DH + d] = val * 0.125f;
                else if (w == 1) g_k[(h * JPAD + row + 2) * DH + d] = val;
                else             g_v[(h * JPAD + row + 2) * DH + d] = val;
            } else {
                C[row * 512 + col] = val;
            }
        }
    }
}

// ---------------- sim = q . k^T, causal tiles only ------------------------------------
__global__ void sim_kernel() {
    const int jt = blockIdx.x;        // 0..16
    const int it = blockIdx.y;        // 0..15
    const int h  = blockIdx.z;
    if (jt > it + 1) return;          // tile fully masked
    __shared__ float Qs[64][65];      // [d][i]
    __shared__ float Ks[64][65];      // [d][j]
    const int tid = threadIdx.x;
    const int tx = tid & 15, ty = tid >> 4;
    const int c = (tid & 15) << 2;    // d base (fixed per thread)
#pragma unroll
    for (int t = 0; t < 4; t++) {
        const int r = (tid >> 4) + t * 16;
        float4 q4 = *(const float4*)&g_q[((h << 10) + it * 64 + r) * DH + c];
        Qs[c + 0][r] = q4.x; Qs[c + 1][r] = q4.y; Qs[c + 2][r] = q4.z; Qs[c + 3][r] = q4.w;
        float4 k4 = *(const float4*)&g_k[(h * JPAD + jt * 64 + r) * DH + c];
        Ks[c + 0][r] = k4.x; Ks[c + 1][r] = k4.y; Ks[c + 2][r] = k4.z; Ks[c + 3][r] = k4.w;
    }
    __syncthreads();
    float acc[4][4] = {};
#pragma unroll 16
    for (int d = 0; d < 64; d++) {
        float ra[4], rb[4];
#pragma unroll
        for (int ii = 0; ii < 4; ii++) ra[ii] = Qs[d][(ty << 2) + ii];
#pragma unroll
        for (int jj = 0; jj < 4; jj++) rb[jj] = Ks[d][(tx << 2) + jj];
#pragma unroll
        for (int ii = 0; ii < 4; ii++)
#pragma unroll
            for (int jj = 0; jj < 4; jj++)
                acc[ii][jj] += ra[ii] * rb[jj];
    }
#pragma unroll
    for (int ii = 0; ii < 4; ii++) {
        const int i = it * 64 + (ty << 2) + ii;
        float* srow = g_s + (size_t)(h * N_TOK + i) * JPAD;
#pragma unroll
        for (int jj = 0; jj < 4; jj++)
            srow[jt * 64 + (tx << 2) + jj] = acc[ii][jj];
    }
}

// ---------------- coordinate descent: one block per (h, i) row ------------------------
__global__ void cd_kernel() {
    const int i = blockIdx.x;
    const int h = blockIdx.y;
    const int jmax = i + 3;                    // nulls(2) + causal keys (j <= i+2)
    float* __restrict__ srow = g_s + (size_t)(h * N_TOK + i) * JPAD;
    const int tid = threadIdx.x;
    __shared__ float red[8];

    float s[5], b[5];
#pragma unroll
    for (int u = 0; u < 5; u++) {
        const int j = tid + u * 256;
        s[u] = (j < jmax) ? srow[j] : 0.0f;
        b[u] = -s[u];
    }

    float a = 0.0f;
    for (int it = 0; it < CD_ITERS; it++) {
        float tm = -3.4e38f;
#pragma unroll
        for (int u = 0; u < 5; u++) {
            const int j = tid + u * 256;
            if (j < jmax) tm = fmaxf(tm, s[u] + b[u]);
        }
        const float m = block_max_256(tm, red);
        float ls = 0.0f;
#pragma unroll
        for (int u = 0; u < 5; u++) {
            const int j = tid + u * 256;
            if (j < jmax) ls += __expf((s[u] + b[u] - m) * INV_EPS);
        }
        const float sum = block_sum_256(ls, red);
        a = EPSF * LOGK - m - EPSF * logf(sum);
#pragma unroll
        for (int u = 0; u < 5; u++) {
            const int j = tid + u * 256;
            if (j < jmax) b[u] = fminf(0.0f, s[u] + a);
        }
    }
    // final probabilities; zero-fill masked + pad so AV gemm needs no guards
#pragma unroll
    for (int u = 0; u < 5; u++) {
        const int j = tid + u * 256;
        if (j < JPAD)
            srow[j] = (j < jmax) ? expf((s[u] + a + b[u]) * INV_EPS) : 0.0f;
    }
}

// ---------------- out = attn . v : 64(i) x 64(d) tiles, reduce over j -----------------
__global__ void av_kernel() {
    const int it = blockIdx.x;   // 0..15
    const int h  = blockIdx.y;
    __shared__ float Ps[64][65];   // [j][i]
    __shared__ float Vs[64][64];   // [j][d]
    const int tid = threadIdx.x;
    const int tx = tid & 15, ty = tid >> 4;
    const int c = (tid & 15) << 2;
    float acc[4][4] = {};
    for (int jt = 0; jt <= it + 1; jt++) {
#pragma unroll
        for (int t = 0; t < 4; t++) {
            const int r = (tid >> 4) + t * 16;
            float4 p4 = *(const float4*)&g_s[(size_t)(h * N_TOK + it * 64 + r) * JPAD + jt * 64 + c];
            Ps[c + 0][r] = p4.x; Ps[c + 1][r] = p4.y; Ps[c + 2][r] = p4.z; Ps[c + 3][r] = p4.w;
            float4 v4 = *(const float4*)&g_v[(h * JPAD + jt * 64 + r) * DH + c];
            *(float4*)&Vs[r][c] = v4;
        }
        __syncthreads();
#pragma unroll 16
        for (int j = 0; j < 64; j++) {
            float ra[4], rb[4];
#pragma unroll
            for (int ii = 0; ii < 4; ii++) ra[ii] = Ps[j][(ty << 2) + ii];
#pragma unroll
            for (int jj = 0; jj < 4; jj++) rb[jj] = Vs[j][(tx << 2) + jj];
#pragma unroll
            for (int ii = 0; ii < 4; ii++)
#pragma unroll
                for (int jj = 0; jj < 4; jj++)
                    acc[ii][jj] += ra[ii] * rb[jj];
        }
        __syncthreads();
    }
#pragma unroll
    for (int ii = 0; ii < 4; ii++) {
        const int row = it * 64 + (ty << 2) + ii;
#pragma unroll
        for (int jj = 0; jj < 4; jj++)
            g_o[row * DIMV + h * DH + (tx << 2) + jj] = acc[ii][jj];
    }
}

// ---------------- launch ----------------
extern "C" void kernel_launch(void* const* d_in, const int* in_sizes, int n_in,
                              void* d_out, int out_size) {
    const float* x       = (const float*)d_in[0];   // (1,1024,512)
    const float* w_qkv   = (const float*)d_in[1];   // (512,1536)
    const float* w_out   = (const float*)d_in[2];   // (512,512)
    const float* null_kv = (const float*)d_in[3];   // (2,8,2,64)
    const float* ln_g    = (const float*)d_in[4];   // (512,)
    const float* ln_b    = (const float*)d_in[5];   // (512,)
    float* out = (float*)d_out;                     // (1,1024,512)

    ln_kernel  <<<N_TOK, 256>>>(x, ln_g, ln_b);
    fill_kernel<<<64, 512>>>(null_kv);
    gemm_kernel<<<dim3(24, 16), 256>>>(w_qkv, nullptr, 1536, 1);   // qkv
    sim_kernel <<<dim3(17, 16, HEADS), 256>>>();
    cd_kernel  <<<dim3(N_TOK, HEADS), 256>>>();
    av_kernel  <<<dim3(16, HEADS), 256>>>();
    gemm_kernel<<<dim3(8, 16), 256>>>(w_out, out, 512, 0);         // projection
}

// round 2
// speedup vs baseline: 1.4656x; 1.4656x over previous
#include <cuda_runtime.h>
#include <math.h>

#define N_TOK 1024
#define DIMV  512
#define HEADS 8
#define DH    64
#define JTOT  1026          // NULL_KV(2) + N_TOK
#define JPAD  1088          // 17 * 64
#define INV_EPS 10.0f
#define EPSF    0.1f
#define LOGK    2.0794415416798357f   // log(8)
#define CD_ITERS 50

// ---------------- scratch (no allocations allowed) ----------------
__device__ float g_xn[N_TOK * DIMV];
__device__ float g_q [HEADS * N_TOK * DH];
__device__ float g_k [HEADS * JPAD * DH];
__device__ float g_v [HEADS * JPAD * DH];
__device__ float g_s [HEADS * N_TOK * JPAD];   // scores, later overwritten with probs
__device__ float g_o [N_TOK * DIMV];           // attention output (n, h*dh)

// ---------------- block reductions (256 threads, 8 warps) ----------------
__device__ __forceinline__ float block_max_256(float v, float* red) {
#pragma unroll
    for (int o = 16; o; o >>= 1) v = fmaxf(v, __shfl_xor_sync(0xffffffffu, v, o));
    __syncthreads();
    if ((threadIdx.x & 31) == 0) red[threadIdx.x >> 5] = v;
    __syncthreads();
    v = red[threadIdx.x & 7];
#pragma unroll
    for (int o = 4; o; o >>= 1) v = fmaxf(v, __shfl_xor_sync(0xffffffffu, v, o));
    return v;
}

__device__ __forceinline__ float block_sum_256(float v, float* red) {
#pragma unroll
    for (int o = 16; o; o >>= 1) v += __shfl_xor_sync(0xffffffffu, v, o);
    __syncthreads();
    if ((threadIdx.x & 31) == 0) red[threadIdx.x >> 5] = v;
    __syncthreads();
    v = red[threadIdx.x & 7];
#pragma unroll
    for (int o = 4; o; o >>= 1) v += __shfl_xor_sync(0xffffffffu, v, o);
    return v;
}

// ---------------- LayerNorm ----------------
__global__ void ln_kernel(const float* __restrict__ x, const float* __restrict__ gam,
                          const float* __restrict__ bet) {
    __shared__ float red[8];
    const int row = blockIdx.x;
    const int tid = threadIdx.x;
    const float v0 = x[row * DIMV + tid];
    const float v1 = x[row * DIMV + tid + 256];
    float s  = v0 + v1;
    float sq = v0 * v0 + v1 * v1;
    s  = block_sum_256(s,  red);
    sq = block_sum_256(sq, red);
    const float mean = s * (1.0f / 512.0f);
    const float var  = sq * (1.0f / 512.0f) - mean * mean;
    const float rstd = rsqrtf(var + 1e-5f);
    g_xn[row * DIMV + tid]       = (v0 - mean) * rstd * gam[tid]       + bet[tid];
    g_xn[row * DIMV + tid + 256] = (v1 - mean) * rstd * gam[tid + 256] + bet[tid + 256];
}

// ---------------- fill null kv rows and zero pad rows ----------------
__global__ void fill_kernel(const float* __restrict__ null_kv) {
    const int idx = blockIdx.x * blockDim.x + threadIdx.x;   // 32768
    const int h = idx >> 12;
    const int r = (idx >> 6) & 63;
    const int d = idx & 63;
    if (r < 2) {
        g_k[(h * JPAD + r) * DH + d] = null_kv[((0 * HEADS + h) * 2 + r) * DH + d];
        g_v[(h * JPAD + r) * DH + d] = null_kv[((1 * HEADS + h) * 2 + r) * DH + d];
    } else {
        const int j = 1024 + r;
        g_k[(h * JPAD + j) * DH + d] = 0.0f;
        g_v[(h * JPAD + j) * DH + d] = 0.0f;
    }
}

// ---------------- QKV GEMM: 128x64 tile, 8x4 micro, M=1024 N=1536 K=512 ---------------
__global__ void gemm_qkv(const float* __restrict__ B) {
    __shared__ float As[16][132];   // [k][row], padded
    __shared__ float Bs[16][64];    // [k][col]
    const float* __restrict__ A = g_xn;
    const int bx = blockIdx.x, by = blockIdx.y, tid = threadIdx.x;
    const int tx = tid & 15, ty = tid >> 4;
    const int ar = tid >> 2, ac = (tid & 3) << 2;    // A: 64 rows per half, 16 k
    const int br = tid >> 4, bc = (tid & 15) << 2;   // B: 16 k x 64 cols
    float acc[8][4] = {};
    for (int k0 = 0; k0 < 512; k0 += 16) {
        float4 a0 = *(const float4*)(A + (by * 128 + ar) * 512 + k0 + ac);
        float4 a1 = *(const float4*)(A + (by * 128 + ar + 64) * 512 + k0 + ac);
        As[ac + 0][ar] = a0.x; As[ac + 1][ar] = a0.y;
        As[ac + 2][ar] = a0.z; As[ac + 3][ar] = a0.w;
        As[ac + 0][ar + 64] = a1.x; As[ac + 1][ar + 64] = a1.y;
        As[ac + 2][ar + 64] = a1.z; As[ac + 3][ar + 64] = a1.w;
        float4 b4 = *(const float4*)(B + (size_t)(k0 + br) * 1536 + bx * 64 + bc);
        *(float4*)&Bs[br][bc] = b4;
        __syncthreads();
#pragma unroll
        for (int kk = 0; kk < 16; kk++) {
            float ra[8], rb[4];
            *(float4*)(ra)     = *(const float4*)&As[kk][ty << 3];
            *(float4*)(ra + 4) = *(const float4*)&As[kk][(ty << 3) + 4];
            *(float4*)rb       = *(const float4*)&Bs[kk][tx << 2];
#pragma unroll
            for (int ii = 0; ii < 8; ii++)
#pragma unroll
                for (int jj = 0; jj < 4; jj++)
                    acc[ii][jj] += ra[ii] * rb[jj];
        }
        __syncthreads();
    }
#pragma unroll
    for (int ii = 0; ii < 8; ii++) {
        const int row = by * 128 + (ty << 3) + ii;
#pragma unroll
        for (int jj = 0; jj < 4; jj++) {
            const int col = bx * 64 + (tx << 2) + jj;
            const float val = acc[ii][jj];
            const int h = (col >> 6) & 7, d = col & 63, w = col >> 9;
            if (w == 0)      g_q[(h * N_TOK + row) * DH + d] = val * 0.125f;
            else if (w == 1) g_k[(h * JPAD + row + 2) * DH + d] = val;
            else             g_v[(h * JPAD + row + 2) * DH + d] = val;
        }
    }
}

// ---------------- out projection GEMM: 64x64 tile, M=1024 N=512 K=512 -----------------
__global__ void gemm_proj(const float* __restrict__ B, float* __restrict__ C) {
    __shared__ float As[16][64];
    __shared__ float Bs[16][64];
    const float* __restrict__ A = g_o;
    const int bx = blockIdx.x, by = blockIdx.y, tid = threadIdx.x;
    const int tx = tid & 15, ty = tid >> 4;
    const int ar = tid >> 2, ac = (tid & 3) << 2;
    const int br = tid >> 4, bc = (tid & 15) << 2;
    float acc[4][4] = {};
    for (int k0 = 0; k0 < 512; k0 += 16) {
        float4 a4 = *(const float4*)(A + (by * 64 + ar) * 512 + k0 + ac);
        As[ac + 0][ar] = a4.x; As[ac + 1][ar] = a4.y;
        As[ac + 2][ar] = a4.z; As[ac + 3][ar] = a4.w;
        float4 b4 = *(const float4*)(B + (size_t)(k0 + br) * 512 + bx * 64 + bc);
        *(float4*)&Bs[br][bc] = b4;
        __syncthreads();
#pragma unroll
        for (int kk = 0; kk < 16; kk++) {
            float ra[4], rb[4];
            *(float4*)ra = *(const float4*)&As[kk][ty << 2];
            *(float4*)rb = *(const float4*)&Bs[kk][tx << 2];
#pragma unroll
            for (int ii = 0; ii < 4; ii++)
#pragma unroll
                for (int jj = 0; jj < 4; jj++)
                    acc[ii][jj] += ra[ii] * rb[jj];
        }
        __syncthreads();
    }
#pragma unroll
    for (int ii = 0; ii < 4; ii++) {
        const int row = by * 64 + (ty << 2) + ii;
#pragma unroll
        for (int jj = 0; jj < 4; jj++)
            C[row * 512 + bx * 64 + (tx << 2) + jj] = acc[ii][jj];
    }
}

// ---------------- sim = q . k^T, causal tiles only ----------------
__global__ void sim_kernel() {
    const int jt = blockIdx.x;
    const int it = blockIdx.y;
    const int h  = blockIdx.z;
    if (jt > it + 1) return;
    __shared__ float Qs[64][65];
    __shared__ float Ks[64][65];
    const int tid = threadIdx.x;
    const int tx = tid & 15, ty = tid >> 4;
    const int c = (tid & 15) << 2;
#pragma unroll
    for (int t = 0; t < 4; t++) {
        const int r = (tid >> 4) + t * 16;
        float4 q4 = *(const float4*)&g_q[((h << 10) + it * 64 + r) * DH + c];
        Qs[c + 0][r] = q4.x; Qs[c + 1][r] = q4.y; Qs[c + 2][r] = q4.z; Qs[c + 3][r] = q4.w;
        float4 k4 = *(const float4*)&g_k[(h * JPAD + jt * 64 + r) * DH + c];
        Ks[c + 0][r] = k4.x; Ks[c + 1][r] = k4.y; Ks[c + 2][r] = k4.z; Ks[c + 3][r] = k4.w;
    }
    __syncthreads();
    float acc[4][4] = {};
#pragma unroll 16
    for (int d = 0; d < 64; d++) {
        float ra[4], rb[4];
#pragma unroll
        for (int ii = 0; ii < 4; ii++) ra[ii] = Qs[d][(ty << 2) + ii];
#pragma unroll
        for (int jj = 0; jj < 4; jj++) rb[jj] = Ks[d][(tx << 2) + jj];
#pragma unroll
        for (int ii = 0; ii < 4; ii++)
#pragma unroll
            for (int jj = 0; jj < 4; jj++)
                acc[ii][jj] += ra[ii] * rb[jj];
    }
#pragma unroll
    for (int ii = 0; ii < 4; ii++) {
        const int i = it * 64 + (ty << 2) + ii;
        float* srow = g_s + (size_t)(h * N_TOK + i) * JPAD;
#pragma unroll
        for (int jj = 0; jj < 4; jj++)
            srow[jt * 64 + (tx << 2) + jj] = acc[ii][jj];
    }
}

// ---------------- coordinate descent: one block per (h, i) row ------------------------
// Single reduction per iteration: m = max(s) fixed once. Provable bounds keep
// exp args in [-c, 0] with sum >= e^-4.85, so no per-iter max reduction needed.
__global__ void cd_kernel() {
    const int i = blockIdx.x;
    const int h = blockIdx.y;
    const int jmax = i + 3;                         // nulls(2) + causal (j <= i+2)
    const int nchunk = (jmax + 255) >> 8;           // 1..5, uniform per block
    float* __restrict__ srow = g_s + (size_t)(h * N_TOK + i) * JPAD;
    const int tid = threadIdx.x;
    __shared__ float red[8];

    float s[5], b[5];
    float tm = -3.4e38f;
#pragma unroll
    for (int u = 0; u < 5; u++) {
        s[u] = 0.0f; b[u] = 0.0f;
        if (u < nchunk) {
            const int j = tid + u * 256;
            if (j < jmax) {
                s[u] = srow[j];
                tm = fmaxf(tm, s[u]);
            }
            b[u] = -s[u];
        }
    }
    const float m = block_max_256(tm, red);

    float a = 0.0f;
    for (int it = 0; it < CD_ITERS; it++) {
        float ls = 0.0f;
#pragma unroll
        for (int u = 0; u < 5; u++) {
            if (u < nchunk) {
                float e = __expf((s[u] + b[u] - m) * INV_EPS);
                if (u == nchunk - 1) {
                    const int j = tid + u * 256;
                    e = (j < jmax) ? e : 0.0f;
                }
                ls += e;
            }
        }
        const float sum = block_sum_256(ls, red);
        a = EPSF * LOGK - EPSF * __logf(sum) - m;
#pragma unroll
        for (int u = 0; u < 5; u++)
            if (u < nchunk) b[u] = fminf(0.0f, s[u] + a);
    }
    // final probabilities; zero-fill masked + pad so AV gemm needs no guards
#pragma unroll
    for (int u = 0; u < 5; u++) {
        const int j = tid + u * 256;
        if (j < JPAD) {
            float val = 0.0f;
            if (u < nchunk && j < jmax)
                val = __expf((s[u] + a + b[u]) * INV_EPS);
            srow[j] = val;
        }
    }
}

// ---------------- out = attn . v ----------------
__global__ void av_kernel() {
    const int it = blockIdx.x;
    const int h  = blockIdx.y;
    __shared__ float Ps[64][65];
    __shared__ float Vs[64][64];
    const int tid = threadIdx.x;
    const int tx = tid & 15, ty = tid >> 4;
    const int c = (tid & 15) << 2;
    float acc[4][4] = {};
    for (int jt = 0; jt <= it + 1; jt++) {
#pragma unroll
        for (int t = 0; t < 4; t++) {
            const int r = (tid >> 4) + t * 16;
            float4 p4 = *(const float4*)&g_s[(size_t)(h * N_TOK + it * 64 + r) * JPAD + jt * 64 + c];
            Ps[c + 0][r] = p4.x; Ps[c + 1][r] = p4.y; Ps[c + 2][r] = p4.z; Ps[c + 3][r] = p4.w;
            float4 v4 = *(const float4*)&g_v[(h * JPAD + jt * 64 + r) * DH + c];
            *(float4*)&Vs[r][c] = v4;
        }
        __syncthreads();
#pragma unroll 16
        for (int j = 0; j < 64; j++) {
            float ra[4], rb[4];
#pragma unroll
            for (int ii = 0; ii < 4; ii++) ra[ii] = Ps[j][(ty << 2) + ii];
#pragma unroll
            for (int jj = 0; jj < 4; jj++) rb[jj] = Vs[j][(tx << 2) + jj];
#pragma unroll
            for (int ii = 0; ii < 4; ii++)
#pragma unroll
                for (int jj = 0; jj < 4; jj++)
                    acc[ii][jj] += ra[ii] * rb[jj];
        }
        __syncthreads();
    }
#pragma unroll
    for (int ii = 0; ii < 4; ii++) {
        const int row = it * 64 + (ty << 2) + ii;
#pragma unroll
        for (int jj = 0; jj < 4; jj++)
            g_o[row * DIMV + h * DH + (tx << 2) + jj] = acc[ii][jj];
    }
}

// ---------------- launch ----------------
extern "C" void kernel_launch(void* const* d_in, const int* in_sizes, int n_in,
                              void* d_out, int out_size) {
    const float* x       = (const float*)d_in[0];
    const float* w_qkv   = (const float*)d_in[1];
    const float* w_out   = (const float*)d_in[2];
    const float* null_kv = (const float*)d_in[3];
    const float* ln_g    = (const float*)d_in[4];
    const float* ln_b    = (const float*)d_in[5];
    float* out = (float*)d_out;

    ln_kernel  <<<N_TOK, 256>>>(x, ln_g, ln_b);
    fill_kernel<<<64, 512>>>(null_kv);
    gemm_qkv   <<<dim3(24, 8), 256>>>(w_qkv);
    sim_kernel <<<dim3(17, 16, HEADS), 256>>>();
    cd_kernel  <<<dim3(N_TOK, HEADS), 256>>>();
    av_kernel  <<<dim3(16, HEADS), 256>>>();
    gemm_proj  <<<dim3(8, 16), 256>>>(w_out, out);
}

// round 3
// speedup vs baseline: 2.0989x; 1.4322x over previous
#include <cuda_runtime.h>
#include <math.h>

#define N_TOK 1024
#define DIMV  512
#define HEADS 8
#define DH    64
#define JTOT  1026          // NULL_KV(2) + N_TOK
#define JPAD  1088          // 17 * 64 = 34 * 32
#define INV_EPS 10.0f
#define EPSF    0.1f
#define LOGK    2.0794415416798357f   // log(8)
#define CD_ITERS 50

// ---------------- scratch (no allocations allowed) ----------------
__device__ float g_xn[N_TOK * DIMV];
__device__ float g_q [HEADS * N_TOK * DH];
__device__ float g_k [HEADS * JPAD * DH];
__device__ float g_v [HEADS * JPAD * DH];
__device__ float g_s [HEADS * N_TOK * JPAD];   // scores, later overwritten with probs
__device__ float g_o [N_TOK * DIMV];           // attention output (n, h*dh)

// ---------------- block reductions (256 threads, 8 warps) ----------------
__device__ __forceinline__ float block_sum_256(float v, float* red) {
#pragma unroll
    for (int o = 16; o; o >>= 1) v += __shfl_xor_sync(0xffffffffu, v, o);
    __syncthreads();
    if ((threadIdx.x & 31) == 0) red[threadIdx.x >> 5] = v;
    __syncthreads();
    v = red[threadIdx.x & 7];
#pragma unroll
    for (int o = 4; o; o >>= 1) v += __shfl_xor_sync(0xffffffffu, v, o);
    return v;
}

// ---------------- LayerNorm ----------------
__global__ void ln_kernel(const float* __restrict__ x, const float* __restrict__ gam,
                          const float* __restrict__ bet) {
    __shared__ float red[8];
    const int row = blockIdx.x;
    const int tid = threadIdx.x;
    const float v0 = x[row * DIMV + tid];
    const float v1 = x[row * DIMV + tid + 256];
    float s  = v0 + v1;
    float sq = v0 * v0 + v1 * v1;
    s  = block_sum_256(s,  red);
    sq = block_sum_256(sq, red);
    const float mean = s * (1.0f / 512.0f);
    const float var  = sq * (1.0f / 512.0f) - mean * mean;
    const float rstd = rsqrtf(var + 1e-5f);
    g_xn[row * DIMV + tid]       = (v0 - mean) * rstd * gam[tid]       + bet[tid];
    g_xn[row * DIMV + tid + 256] = (v1 - mean) * rstd * gam[tid + 256] + bet[tid + 256];
}

// ---------------- fill null kv rows and zero pad rows ----------------
__global__ void fill_kernel(const float* __restrict__ null_kv) {
    const int idx = blockIdx.x * blockDim.x + threadIdx.x;   // 32768
    const int h = idx >> 12;
    const int r = (idx >> 6) & 63;
    const int d = idx & 63;
    if (r < 2) {
        g_k[(h * JPAD + r) * DH + d] = null_kv[((0 * HEADS + h) * 2 + r) * DH + d];
        g_v[(h * JPAD + r) * DH + d] = null_kv[((1 * HEADS + h) * 2 + r) * DH + d];
    } else {
        const int j = 1024 + r;
        g_k[(h * JPAD + j) * DH + d] = 0.0f;
        g_v[(h * JPAD + j) * DH + d] = 0.0f;
    }
}

// ---------------- QKV GEMM: 128x64 tile, 8x4 micro, M=1024 N=1536 K=512 ---------------
__global__ void gemm_qkv(const float* __restrict__ B) {
    __shared__ float As[16][132];
    __shared__ float Bs[16][64];
    const float* __restrict__ A = g_xn;
    const int bx = blockIdx.x, by = blockIdx.y, tid = threadIdx.x;
    const int tx = tid & 15, ty = tid >> 4;
    const int ar = tid >> 2, ac = (tid & 3) << 2;
    const int br = tid >> 4, bc = (tid & 15) << 2;
    float acc[8][4] = {};
    for (int k0 = 0; k0 < 512; k0 += 16) {
        float4 a0 = *(const float4*)(A + (by * 128 + ar) * 512 + k0 + ac);
        float4 a1 = *(const float4*)(A + (by * 128 + ar + 64) * 512 + k0 + ac);
        As[ac + 0][ar] = a0.x; As[ac + 1][ar] = a0.y;
        As[ac + 2][ar] = a0.z; As[ac + 3][ar] = a0.w;
        As[ac + 0][ar + 64] = a1.x; As[ac + 1][ar + 64] = a1.y;
        As[ac + 2][ar + 64] = a1.z; As[ac + 3][ar + 64] = a1.w;
        float4 b4 = *(const float4*)(B + (size_t)(k0 + br) * 1536 + bx * 64 + bc);
        *(float4*)&Bs[br][bc] = b4;
        __syncthreads();
#pragma unroll
        for (int kk = 0; kk < 16; kk++) {
            float ra[8], rb[4];
            *(float4*)(ra)     = *(const float4*)&As[kk][ty << 3];
            *(float4*)(ra + 4) = *(const float4*)&As[kk][(ty << 3) + 4];
            *(float4*)rb       = *(const float4*)&Bs[kk][tx << 2];
#pragma unroll
            for (int ii = 0; ii < 8; ii++)
#pragma unroll
                for (int jj = 0; jj < 4; jj++)
                    acc[ii][jj] += ra[ii] * rb[jj];
        }
        __syncthreads();
    }
#pragma unroll
    for (int ii = 0; ii < 8; ii++) {
        const int row = by * 128 + (ty << 3) + ii;
#pragma unroll
        for (int jj = 0; jj < 4; jj++) {
            const int col = bx * 64 + (tx << 2) + jj;
            const float val = acc[ii][jj];
            const int h = (col >> 6) & 7, d = col & 63, w = col >> 9;
            if (w == 0)      g_q[(h * N_TOK + row) * DH + d] = val * 0.125f;
            else if (w == 1) g_k[(h * JPAD + row + 2) * DH + d] = val;
            else             g_v[(h * JPAD + row + 2) * DH + d] = val;
        }
    }
}

// ---------------- out projection GEMM: 64x64 tile, M=1024 N=512 K=512 -----------------
__global__ void gemm_proj(const float* __restrict__ B, float* __restrict__ C) {
    __shared__ float As[16][64];
    __shared__ float Bs[16][64];
    const float* __restrict__ A = g_o;
    const int bx = blockIdx.x, by = blockIdx.y, tid = threadIdx.x;
    const int tx = tid & 15, ty = tid >> 4;
    const int ar = tid >> 2, ac = (tid & 3) << 2;
    const int br = tid >> 4, bc = (tid & 15) << 2;
    float acc[4][4] = {};
    for (int k0 = 0; k0 < 512; k0 += 16) {
        float4 a4 = *(const float4*)(A + (by * 64 + ar) * 512 + k0 + ac);
        As[ac + 0][ar] = a4.x; As[ac + 1][ar] = a4.y;
        As[ac + 2][ar] = a4.z; As[ac + 3][ar] = a4.w;
        float4 b4 = *(const float4*)(B + (size_t)(k0 + br) * 512 + bx * 64 + bc);
        *(float4*)&Bs[br][bc] = b4;
        __syncthreads();
#pragma unroll
        for (int kk = 0; kk < 16; kk++) {
            float ra[4], rb[4];
            *(float4*)ra = *(const float4*)&As[kk][ty << 2];
            *(float4*)rb = *(const float4*)&Bs[kk][tx << 2];
#pragma unroll
            for (int ii = 0; ii < 4; ii++)
#pragma unroll
                for (int jj = 0; jj < 4; jj++)
                    acc[ii][jj] += ra[ii] * rb[jj];
        }
        __syncthreads();
    }
#pragma unroll
    for (int ii = 0; ii < 4; ii++) {
        const int row = by * 64 + (ty << 2) + ii;
#pragma unroll
        for (int jj = 0; jj < 4; jj++)
            C[row * 512 + bx * 64 + (tx << 2) + jj] = acc[ii][jj];
    }
}

// ---------------- sim = q . k^T, causal tiles only ----------------
__global__ void sim_kernel() {
    const int jt = blockIdx.x;
    const int it = blockIdx.y;
    const int h  = blockIdx.z;
    if (jt > it + 1) return;
    __shared__ float Qs[64][65];
    __shared__ float Ks[64][65];
    const int tid = threadIdx.x;
    const int tx = tid & 15, ty = tid >> 4;
    const int c = (tid & 15) << 2;
#pragma unroll
    for (int t = 0; t < 4; t++) {
        const int r = (tid >> 4) + t * 16;
        float4 q4 = *(const float4*)&g_q[((h << 10) + it * 64 + r) * DH + c];
        Qs[c + 0][r] = q4.x; Qs[c + 1][r] = q4.y; Qs[c + 2][r] = q4.z; Qs[c + 3][r] = q4.w;
        float4 k4 = *(const float4*)&g_k[(h * JPAD + jt * 64 + r) * DH + c];
        Ks[c + 0][r] = k4.x; Ks[c + 1][r] = k4.y; Ks[c + 2][r] = k4.z; Ks[c + 3][r] = k4.w;
    }
    __syncthreads();
    float acc[4][4] = {};
#pragma unroll 16
    for (int d = 0; d < 64; d++) {
        float ra[4], rb[4];
#pragma unroll
        for (int ii = 0; ii < 4; ii++) ra[ii] = Qs[d][(ty << 2) + ii];
#pragma unroll
        for (int jj = 0; jj < 4; jj++) rb[jj] = Ks[d][(tx << 2) + jj];
#pragma unroll
        for (int ii = 0; ii < 4; ii++)
#pragma unroll
            for (int jj = 0; jj < 4; jj++)
                acc[ii][jj] += ra[ii] * rb[jj];
    }
#pragma unroll
    for (int ii = 0; ii < 4; ii++) {
        const int i = it * 64 + (ty << 2) + ii;
        float* srow = g_s + (size_t)(h * N_TOK + i) * JPAD;
#pragma unroll
        for (int jj = 0; jj < 4; jj++)
            srow[jt * 64 + (tx << 2) + jj] = acc[ii][jj];
    }
}

// ---------------- coordinate descent: ONE WARP per (h, i) row -------------------------
// Key identity: for t>=2, b = min(0, s+a), so exp((s+b-m)/eps) = min(E1, w*E1^2)
// with E1 = exp((s-m)/eps) precomputed and w = exp((a+m)/eps) scalar per iteration.
// Iter 1 is closed-form: a1 = eps*(log k - log jmax). No MUFU in the inner loop;
// reductions are 5 warp shuffles (no syncthreads, no smem).
__global__ void cd_kernel() {
    const int g    = (blockIdx.x * blockDim.x + threadIdx.x) >> 5;  // row id 0..8191
    const int lane = threadIdx.x & 31;
    const int h = g >> 10, i = g & 1023;
    const int jmax = i + 3;                    // nulls(2) + causal (j <= i+2)
    const int nchunk = (jmax + 31) >> 5;       // 1..33, warp-uniform
    float* __restrict__ srow = g_s + (size_t)(h * N_TOK + i) * JPAD;

    // load s into E1[], find max, transform to E1 = exp((s-m)/eps)
    float E1[33];
    float tm = -3.4e38f;
#pragma unroll
    for (int u = 0; u < 33; u++) {
        E1[u] = -3.4e38f;
        if (u < nchunk) {
            const int j = lane + u * 32;
            if (j < jmax) { E1[u] = srow[j]; tm = fmaxf(tm, E1[u]); }
        }
    }
#pragma unroll
    for (int o = 16; o; o >>= 1) tm = fmaxf(tm, __shfl_xor_sync(0xffffffffu, tm, o));
    const float m = tm;
#pragma unroll
    for (int u = 0; u < 33; u++)
        if (u < nchunk)
            E1[u] = (E1[u] > -3.0e38f) ? __expf((E1[u] - m) * INV_EPS) : 0.0f;

    // iteration 1 closed form
    float a = EPSF * (LOGK - __logf((float)jmax));

    // iterations 2..50
    for (int it = 1; it < CD_ITERS; it++) {
        const float w = __expf((a + m) * INV_EPS);
        float ls0 = 0.0f, ls1 = 0.0f;
#pragma unroll
        for (int u = 0; u < 33; u++) {
            if (u < nchunk) {
                const float e = E1[u];
                const float c = fminf(e, w * (e * e));
                if (u & 1) ls1 += c; else ls0 += c;
            }
        }
        float ls = ls0 + ls1;
#pragma unroll
        for (int o = 16; o; o >>= 1) ls += __shfl_xor_sync(0xffffffffu, ls, o);
        a = EPSF * LOGK - m - EPSF * __logf(ls);
    }

    // final probs: p = min(Eu, Eu^2), Eu = w*E1; zero-fill masked + pad
    const float w = __expf((a + m) * INV_EPS);
#pragma unroll
    for (int u = 0; u < 34; u++) {
        const int j = lane + u * 32;            // < 1088 always
        float val = 0.0f;
        if (u < 33 && u < nchunk) {
            const float eu = w * E1[u];
            val = fminf(eu, eu * eu);
        }
        srow[j] = val;
    }
}

// ---------------- out = attn . v ----------------
__global__ void av_kernel() {
    const int it = blockIdx.x;
    const int h  = blockIdx.y;
    __shared__ float Ps[64][65];
    __shared__ float Vs[64][64];
    const int tid = threadIdx.x;
    const int tx = tid & 15, ty = tid >> 4;
    const int c = (tid & 15) << 2;
    float acc[4][4] = {};
    for (int jt = 0; jt <= it + 1; jt++) {
#pragma unroll
        for (int t = 0; t < 4; t++) {
            const int r = (tid >> 4) + t * 16;
            float4 p4 = *(const float4*)&g_s[(size_t)(h * N_TOK + it * 64 + r) * JPAD + jt * 64 + c];
            Ps[c + 0][r] = p4.x; Ps[c + 1][r] = p4.y; Ps[c + 2][r] = p4.z; Ps[c + 3][r] = p4.w;
            float4 v4 = *(const float4*)&g_v[(h * JPAD + jt * 64 + r) * DH + c];
            *(float4*)&Vs[r][c] = v4;
        }
        __syncthreads();
#pragma unroll 16
        for (int j = 0; j < 64; j++) {
            float ra[4], rb[4];
#pragma unroll
            for (int ii = 0; ii < 4; ii++) ra[ii] = Ps[j][(ty << 2) + ii];
#pragma unroll
            for (int jj = 0; jj < 4; jj++) rb[jj] = Vs[j][(tx << 2) + jj];
#pragma unroll
            for (int ii = 0; ii < 4; ii++)
#pragma unroll
                for (int jj = 0; jj < 4; jj++)
                    acc[ii][jj] += ra[ii] * rb[jj];
        }
        __syncthreads();
    }
#pragma unroll
    for (int ii = 0; ii < 4; ii++) {
        const int row = it * 64 + (ty << 2) + ii;
#pragma unroll
        for (int jj = 0; jj < 4; jj++)
            g_o[row * DIMV + h * DH + (tx << 2) + jj] = acc[ii][jj];
    }
}

// ---------------- launch ----------------
extern "C" void kernel_launch(void* const* d_in, const int* in_sizes, int n_in,
                              void* d_out, int out_size) {
    const float* x       = (const float*)d_in[0];
    const float* w_qkv   = (const float*)d_in[1];
    const float* w_out   = (const float*)d_in[2];
    const float* null_kv = (const float*)d_in[3];
    const float* ln_g    = (const float*)d_in[4];
    const float* ln_b    = (const float*)d_in[5];
    float* out = (float*)d_out;

    ln_kernel  <<<N_TOK, 256>>>(x, ln_g, ln_b);
    fill_kernel<<<64, 512>>>(null_kv);
    gemm_qkv   <<<dim3(24, 8), 256>>>(w_qkv);
    sim_kernel <<<dim3(17, 16, HEADS), 256>>>();
    cd_kernel  <<<2048, 128>>>();               // 4 warps/block, 1 row/warp
    av_kernel  <<<dim3(16, HEADS), 256>>>();
    gemm_proj  <<<dim3(8, 16), 256>>>(w_out, out);
}

// round 4
// speedup vs baseline: 3.1249x; 1.4888x over previous
#include <cuda_runtime.h>
#include <math.h>

#define N_TOK 1024
#define DIMV  512
#define HEADS 8
#define DH    64
#define JTOT  1026          // NULL_KV(2) + N_TOK
#define JPAD  1088          // 17 * 64 = 34 * 32
#define INV_EPS 10.0f
#define EPSF    0.1f
#define LOGK    2.0794415416798357f   // log(8)
#define CD_ITERS 50

// ---------------- scratch (no allocations allowed) ----------------
__device__ float g_xn[N_TOK * DIMV];
__device__ float g_q [HEADS * N_TOK * DH];
__device__ float g_k [HEADS * JPAD * DH];
__device__ float g_v [HEADS * JPAD * DH];
__device__ float g_s [HEADS * N_TOK * JPAD];   // scores, later overwritten with probs
__device__ float g_o [N_TOK * DIMV];           // attention output (n, h*dh)

__device__ __forceinline__ float block_sum_256(float v, float* red) {
#pragma unroll
    for (int o = 16; o; o >>= 1) v += __shfl_xor_sync(0xffffffffu, v, o);
    __syncthreads();
    if ((threadIdx.x & 31) == 0) red[threadIdx.x >> 5] = v;
    __syncthreads();
    v = red[threadIdx.x & 7];
#pragma unroll
    for (int o = 4; o; o >>= 1) v += __shfl_xor_sync(0xffffffffu, v, o);
    return v;
}

// ---------------- fused LayerNorm (blocks 0..1023) + null-kv/pad fill (1024..1151) ----
__global__ void ln_fill_kernel(const float* __restrict__ x, const float* __restrict__ gam,
                               const float* __restrict__ bet,
                               const float* __restrict__ null_kv) {
    if (blockIdx.x >= 1024) {
        const int idx = (blockIdx.x - 1024) * 256 + threadIdx.x;  // 0..32767
        const int h = idx >> 12;
        const int r = (idx >> 6) & 63;
        const int d = idx & 63;
        if (r < 2) {
            g_k[(h * JPAD + r) * DH + d] = null_kv[((0 * HEADS + h) * 2 + r) * DH + d];
            g_v[(h * JPAD + r) * DH + d] = null_kv[((1 * HEADS + h) * 2 + r) * DH + d];
        } else {
            const int j = 1024 + r;
            g_k[(h * JPAD + j) * DH + d] = 0.0f;
            g_v[(h * JPAD + j) * DH + d] = 0.0f;
        }
        return;
    }
    __shared__ float red[8];
    const int row = blockIdx.x;
    const int tid = threadIdx.x;
    const float v0 = x[row * DIMV + tid];
    const float v1 = x[row * DIMV + tid + 256];
    float s  = v0 + v1;
    float sq = v0 * v0 + v1 * v1;
    s  = block_sum_256(s,  red);
    sq = block_sum_256(sq, red);
    const float mean = s * (1.0f / 512.0f);
    const float var  = sq * (1.0f / 512.0f) - mean * mean;
    const float rstd = rsqrtf(var + 1e-5f);
    g_xn[row * DIMV + tid]       = (v0 - mean) * rstd * gam[tid]       + bet[tid];
    g_xn[row * DIMV + tid + 256] = (v1 - mean) * rstd * gam[tid + 256] + bet[tid + 256];
}

// ---------------- QKV GEMM: 128x64 tile, 8x4 micro, reg-staged double buffer ----------
__global__ void gemm_qkv(const float* __restrict__ B) {
    __shared__ float As[16][132];
    __shared__ float Bs[16][64];
    const float* __restrict__ A = g_xn;
    const int bx = blockIdx.x, by = blockIdx.y, tid = threadIdx.x;
    const int tx = tid & 15, ty = tid >> 4;
    const int ar = tid >> 2, ac = (tid & 3) << 2;
    const int br = tid >> 4, bc = (tid & 15) << 2;
    float acc[8][4] = {};

    float4 a0 = *(const float4*)(A + (by * 128 + ar) * 512 + ac);
    float4 a1 = *(const float4*)(A + (by * 128 + ar + 64) * 512 + ac);
    float4 b0 = *(const float4*)(B + (size_t)br * 1536 + bx * 64 + bc);

    for (int k0 = 0; k0 < 512; k0 += 16) {
        As[ac + 0][ar] = a0.x; As[ac + 1][ar] = a0.y;
        As[ac + 2][ar] = a0.z; As[ac + 3][ar] = a0.w;
        As[ac + 0][ar + 64] = a1.x; As[ac + 1][ar + 64] = a1.y;
        As[ac + 2][ar + 64] = a1.z; As[ac + 3][ar + 64] = a1.w;
        *(float4*)&Bs[br][bc] = b0;
        __syncthreads();
        if (k0 + 16 < 512) {
            a0 = *(const float4*)(A + (by * 128 + ar) * 512 + k0 + 16 + ac);
            a1 = *(const float4*)(A + (by * 128 + ar + 64) * 512 + k0 + 16 + ac);
            b0 = *(const float4*)(B + (size_t)(k0 + 16 + br) * 1536 + bx * 64 + bc);
        }
#pragma unroll
        for (int kk = 0; kk < 16; kk++) {
            float ra[8], rb[4];
            *(float4*)(ra)     = *(const float4*)&As[kk][ty << 3];
            *(float4*)(ra + 4) = *(const float4*)&As[kk][(ty << 3) + 4];
            *(float4*)rb       = *(const float4*)&Bs[kk][tx << 2];
#pragma unroll
            for (int ii = 0; ii < 8; ii++)
#pragma unroll
                for (int jj = 0; jj < 4; jj++)
                    acc[ii][jj] += ra[ii] * rb[jj];
        }
        __syncthreads();
    }
#pragma unroll
    for (int ii = 0; ii < 8; ii++) {
        const int row = by * 128 + (ty << 3) + ii;
#pragma unroll
        for (int jj = 0; jj < 4; jj++) {
            const int col = bx * 64 + (tx << 2) + jj;
            const float val = acc[ii][jj];
            const int h = (col >> 6) & 7, d = col & 63, w = col >> 9;
            if (w == 0)      g_q[(h * N_TOK + row) * DH + d] = val * 0.125f;
            else if (w == 1) g_k[(h * JPAD + row + 2) * DH + d] = val;
            else             g_v[(h * JPAD + row + 2) * DH + d] = val;
        }
    }
}

// ---------------- out projection GEMM: 64x64 tile, reg-staged double buffer -----------
__global__ void gemm_proj(const float* __restrict__ B, float* __restrict__ C) {
    __shared__ float As[16][64];
    __shared__ float Bs[16][64];
    const float* __restrict__ A = g_o;
    const int bx = blockIdx.x, by = blockIdx.y, tid = threadIdx.x;
    const int tx = tid & 15, ty = tid >> 4;
    const int ar = tid >> 2, ac = (tid & 3) << 2;
    const int br = tid >> 4, bc = (tid & 15) << 2;
    float acc[4][4] = {};

    float4 a4 = *(const float4*)(A + (by * 64 + ar) * 512 + ac);
    float4 b4 = *(const float4*)(B + (size_t)br * 512 + bx * 64 + bc);

    for (int k0 = 0; k0 < 512; k0 += 16) {
        As[ac + 0][ar] = a4.x; As[ac + 1][ar] = a4.y;
        As[ac + 2][ar] = a4.z; As[ac + 3][ar] = a4.w;
        *(float4*)&Bs[br][bc] = b4;
        __syncthreads();
        if (k0 + 16 < 512) {
            a4 = *(const float4*)(A + (by * 64 + ar) * 512 + k0 + 16 + ac);
            b4 = *(const float4*)(B + (size_t)(k0 + 16 + br) * 512 + bx * 64 + bc);
        }
#pragma unroll
        for (int kk = 0; kk < 16; kk++) {
            float ra[4], rb[4];
            *(float4*)ra = *(const float4*)&As[kk][ty << 2];
            *(float4*)rb = *(const float4*)&Bs[kk][tx << 2];
#pragma unroll
            for (int ii = 0; ii < 4; ii++)
#pragma unroll
                for (int jj = 0; jj < 4; jj++)
                    acc[ii][jj] += ra[ii] * rb[jj];
        }
        __syncthreads();
    }
#pragma unroll
    for (int ii = 0; ii < 4; ii++) {
        const int row = by * 64 + (ty << 2) + ii;
#pragma unroll
        for (int jj = 0; jj < 4; jj++)
            C[row * 512 + bx * 64 + (tx << 2) + jj] = acc[ii][jj];
    }
}

// ---------------- sim = q . k^T, causal tiles only ----------------
__global__ void sim_kernel() {
    const int jt = blockIdx.x;
    const int it = blockIdx.y;
    const int h  = blockIdx.z;
    if (jt > it + 1) return;
    __shared__ float Qs[64][65];
    __shared__ float Ks[64][65];
    const int tid = threadIdx.x;
    const int tx = tid & 15, ty = tid >> 4;
    const int c = (tid & 15) << 2;
#pragma unroll
    for (int t = 0; t < 4; t++) {
        const int r = (tid >> 4) + t * 16;
        float4 q4 = *(const float4*)&g_q[((h << 10) + it * 64 + r) * DH + c];
        Qs[c + 0][r] = q4.x; Qs[c + 1][r] = q4.y; Qs[c + 2][r] = q4.z; Qs[c + 3][r] = q4.w;
        float4 k4 = *(const float4*)&g_k[(h * JPAD + jt * 64 + r) * DH + c];
        Ks[c + 0][r] = k4.x; Ks[c + 1][r] = k4.y; Ks[c + 2][r] = k4.z; Ks[c + 3][r] = k4.w;
    }
    __syncthreads();
    float acc[4][4] = {};
#pragma unroll 16
    for (int d = 0; d < 64; d++) {
        float ra[4], rb[4];
#pragma unroll
        for (int ii = 0; ii < 4; ii++) ra[ii] = Qs[d][(ty << 2) + ii];
#pragma unroll
        for (int jj = 0; jj < 4; jj++) rb[jj] = Ks[d][(tx << 2) + jj];
#pragma unroll
        for (int ii = 0; ii < 4; ii++)
#pragma unroll
            for (int jj = 0; jj < 4; jj++)
                acc[ii][jj] += ra[ii] * rb[jj];
    }
#pragma unroll
    for (int ii = 0; ii < 4; ii++) {
        const int i = it * 64 + (ty << 2) + ii;
        float* srow = g_s + (size_t)(h * N_TOK + i) * JPAD;
#pragma unroll
        for (int jj = 0; jj < 4; jj++)
            srow[jt * 64 + (tx << 2) + jj] = acc[ii][jj];
    }
}

// ---------------- coordinate descent: ONE WARP per (h, i) row -------------------------
// b = min(0, s+a) for t>=2  =>  exp((s+b-m)/eps) = min(E1, w*E1^2), E1 precomputed,
// w scalar per iteration. Iter 1 closed-form. Fixed point is on scalar `a` only ->
// warp-uniform early exit when |da| < 5e-7 (further iterations are numerical no-ops).
__global__ void cd_kernel() {
    const int g    = (blockIdx.x * blockDim.x + threadIdx.x) >> 5;  // row id 0..8191
    const int lane = threadIdx.x & 31;
    const int h = g >> 10, i = g & 1023;
    const int jmax = i + 3;
    const int nchunk = (jmax + 31) >> 5;       // 1..33, warp-uniform
    float* __restrict__ srow = g_s + (size_t)(h * N_TOK + i) * JPAD;

    float E1[33];
    float tm = -3.4e38f;
#pragma unroll
    for (int u = 0; u < 33; u++) {
        E1[u] = -3.4e38f;
        if (u < nchunk) {
            const int j = lane + u * 32;
            if (j < jmax) { E1[u] = srow[j]; tm = fmaxf(tm, E1[u]); }
        }
    }
#pragma unroll
    for (int o = 16; o; o >>= 1) tm = fmaxf(tm, __shfl_xor_sync(0xffffffffu, tm, o));
    const float m = tm;
#pragma unroll
    for (int u = 0; u < 33; u++)
        if (u < nchunk)
            E1[u] = (E1[u] > -3.0e38f) ? __expf((E1[u] - m) * INV_EPS) : 0.0f;

    float a = EPSF * (LOGK - __logf((float)jmax));   // iteration 1 closed form

    for (int it = 1; it < CD_ITERS; it++) {
        const float w = __expf((a + m) * INV_EPS);
        float ls0 = 0.0f, ls1 = 0.0f;
#pragma unroll
        for (int u = 0; u < 33; u++) {
            if (u < nchunk) {
                const float e = E1[u];
                const float c = fminf(e, w * (e * e));
                if (u & 1) ls1 += c; else ls0 += c;
            }
        }
        float ls = ls0 + ls1;
#pragma unroll
        for (int o = 16; o; o >>= 1) ls += __shfl_xor_sync(0xffffffffu, ls, o);
        const float a_new = EPSF * LOGK - m - EPSF * __logf(ls);
        const float da = fabsf(a_new - a);
        a = a_new;
        if (da < 5e-7f) break;                 // warp-uniform (ls identical on all lanes)
    }

    const float w = __expf((a + m) * INV_EPS);
#pragma unroll
    for (int u = 0; u < 34; u++) {
        const int j = lane + u * 32;
        float val = 0.0f;
        if (u < 33 && u < nchunk) {
            const float eu = w * E1[u];
            val = fminf(eu, eu * eu);
        }
        srow[j] = val;
    }
}

// ---------------- out = attn . v ----------------
__global__ void av_kernel() {
    const int it = blockIdx.x;
    const int h  = blockIdx.y;
    __shared__ float Ps[64][65];
    __shared__ float Vs[64][64];
    const int tid = threadIdx.x;
    const int tx = tid & 15, ty = tid >> 4;
    const int c = (tid & 15) << 2;
    float acc[4][4] = {};
    for (int jt = 0; jt <= it + 1; jt++) {
#pragma unroll
        for (int t = 0; t < 4; t++) {
            const int r = (tid >> 4) + t * 16;
            float4 p4 = *(const float4*)&g_s[(size_t)(h * N_TOK + it * 64 + r) * JPAD + jt * 64 + c];
            Ps[c + 0][r] = p4.x; Ps[c + 1][r] = p4.y; Ps[c + 2][r] = p4.z; Ps[c + 3][r] = p4.w;
            float4 v4 = *(const float4*)&g_v[(h * JPAD + jt * 64 + r) * DH + c];
            *(float4*)&Vs[r][c] = v4;
        }
        __syncthreads();
#pragma unroll 16
        for (int j = 0; j < 64; j++) {
            float ra[4], rb[4];
#pragma unroll
            for (int ii = 0; ii < 4; ii++) ra[ii] = Ps[j][(ty << 2) + ii];
#pragma unroll
            for (int jj = 0; jj < 4; jj++) rb[jj] = Vs[j][(tx << 2) + jj];
#pragma unroll
            for (int ii = 0; ii < 4; ii++)
#pragma unroll
                for (int jj = 0; jj < 4; jj++)
                    acc[ii][jj] += ra[ii] * rb[jj];
        }
        __syncthreads();
    }
#pragma unroll
    for (int ii = 0; ii < 4; ii++) {
        const int row = it * 64 + (ty << 2) + ii;
#pragma unroll
        for (int jj = 0; jj < 4; jj++)
            g_o[row * DIMV + h * DH + (tx << 2) + jj] = acc[ii][jj];
    }
}

// ---------------- launch ----------------
extern "C" void kernel_launch(void* const* d_in, const int* in_sizes, int n_in,
                              void* d_out, int out_size) {
    const float* x       = (const float*)d_in[0];
    const float* w_qkv   = (const float*)d_in[1];
    const float* w_out   = (const float*)d_in[2];
    const float* null_kv = (const float*)d_in[3];
    const float* ln_g    = (const float*)d_in[4];
    const float* ln_b    = (const float*)d_in[5];
    float* out = (float*)d_out;

    ln_fill_kernel<<<1152, 256>>>(x, ln_g, ln_b, null_kv);
    gemm_qkv   <<<dim3(24, 8), 256>>>(w_qkv);
    sim_kernel <<<dim3(17, 16, HEADS), 256>>>();
    cd_kernel  <<<2048, 128>>>();
    av_kernel  <<<dim3(16, HEADS), 256>>>();
    gemm_proj  <<<dim3(8, 16), 256>>>(w_out, out);
}

// round 5
// speedup vs baseline: 3.6662x; 1.1732x over previous
#include <cuda_runtime.h>
#include <math.h>

#define N_TOK 1024
#define DIMV  512
#define HEADS 8
#define DH    64
#define JTOT  1026
#define JPAD  1088          // 17 * 64 = 34 * 32
#define INV_EPS 10.0f
#define EPSF    0.1f
#define LOGK    2.0794415416798357f   // log(8)
#define CD_ITERS 50

// ---------------- scratch ----------------
__device__ float g_xn[N_TOK * DIMV];
__device__ float g_q [HEADS * N_TOK * DH];
__device__ float g_k [HEADS * JPAD * DH];
__device__ float g_v [HEADS * JPAD * DH];
__device__ float g_s [HEADS * N_TOK * JPAD];
__device__ float g_o [N_TOK * DIMV];
__device__ float g_o2[N_TOK * DIMV];

__device__ __forceinline__ float block_sum_256(float v, float* red) {
#pragma unroll
    for (int o = 16; o; o >>= 1) v += __shfl_xor_sync(0xffffffffu, v, o);
    __syncthreads();
    if ((threadIdx.x & 31) == 0) red[threadIdx.x >> 5] = v;
    __syncthreads();
    v = red[threadIdx.x & 7];
#pragma unroll
    for (int o = 4; o; o >>= 1) v += __shfl_xor_sync(0xffffffffu, v, o);
    return v;
}

// ---------------- fused LayerNorm + null-kv/pad fill ----------------
__global__ void ln_fill_kernel(const float* __restrict__ x, const float* __restrict__ gam,
                               const float* __restrict__ bet,
                               const float* __restrict__ null_kv) {
    if (blockIdx.x >= 1024) {
        const int idx = (blockIdx.x - 1024) * 256 + threadIdx.x;
        const int h = idx >> 12;
        const int r = (idx >> 6) & 63;
        const int d = idx & 63;
        if (r < 2) {
            g_k[(h * JPAD + r) * DH + d] = null_kv[((0 * HEADS + h) * 2 + r) * DH + d];
            g_v[(h * JPAD + r) * DH + d] = null_kv[((1 * HEADS + h) * 2 + r) * DH + d];
        } else {
            const int j = 1024 + r;
            g_k[(h * JPAD + j) * DH + d] = 0.0f;
            g_v[(h * JPAD + j) * DH + d] = 0.0f;
        }
        return;
    }
    __shared__ float red[8];
    const int row = blockIdx.x;
    const int tid = threadIdx.x;
    const float v0 = x[row * DIMV + tid];
    const float v1 = x[row * DIMV + tid + 256];
    float s  = v0 + v1;
    float sq = v0 * v0 + v1 * v1;
    s  = block_sum_256(s,  red);
    sq = block_sum_256(sq, red);
    const float mean = s * (1.0f / 512.0f);
    const float var  = sq * (1.0f / 512.0f) - mean * mean;
    const float rstd = rsqrtf(var + 1e-5f);
    g_xn[row * DIMV + tid]       = (v0 - mean) * rstd * gam[tid]       + bet[tid];
    g_xn[row * DIMV + tid + 256] = (v1 - mean) * rstd * gam[tid + 256] + bet[tid + 256];
}

// ---------------- QKV GEMM: 128x64 tile, 8x4 micro, reg-staged double buffer ----------
__global__ void gemm_qkv(const float* __restrict__ B) {
    __shared__ float As[16][132];
    __shared__ float Bs[16][64];
    const float* __restrict__ A = g_xn;
    const int bx = blockIdx.x, by = blockIdx.y, tid = threadIdx.x;
    const int tx = tid & 15, ty = tid >> 4;
    const int ar = tid >> 2, ac = (tid & 3) << 2;
    const int br = tid >> 4, bc = (tid & 15) << 2;
    float acc[8][4] = {};

    float4 a0 = *(const float4*)(A + (by * 128 + ar) * 512 + ac);
    float4 a1 = *(const float4*)(A + (by * 128 + ar + 64) * 512 + ac);
    float4 b0 = *(const float4*)(B + (size_t)br * 1536 + bx * 64 + bc);

    for (int k0 = 0; k0 < 512; k0 += 16) {
        As[ac + 0][ar] = a0.x; As[ac + 1][ar] = a0.y;
        As[ac + 2][ar] = a0.z; As[ac + 3][ar] = a0.w;
        As[ac + 0][ar + 64] = a1.x; As[ac + 1][ar + 64] = a1.y;
        As[ac + 2][ar + 64] = a1.z; As[ac + 3][ar + 64] = a1.w;
        *(float4*)&Bs[br][bc] = b0;
        __syncthreads();
        if (k0 + 16 < 512) {
            a0 = *(const float4*)(A + (by * 128 + ar) * 512 + k0 + 16 + ac);
            a1 = *(const float4*)(A + (by * 128 + ar + 64) * 512 + k0 + 16 + ac);
            b0 = *(const float4*)(B + (size_t)(k0 + 16 + br) * 1536 + bx * 64 + bc);
        }
#pragma unroll
        for (int kk = 0; kk < 16; kk++) {
            float ra[8], rb[4];
            *(float4*)(ra)     = *(const float4*)&As[kk][ty << 3];
            *(float4*)(ra + 4) = *(const float4*)&As[kk][(ty << 3) + 4];
            *(float4*)rb       = *(const float4*)&Bs[kk][tx << 2];
#pragma unroll
            for (int ii = 0; ii < 8; ii++)
#pragma unroll
                for (int jj = 0; jj < 4; jj++)
                    acc[ii][jj] += ra[ii] * rb[jj];
        }
        __syncthreads();
    }
#pragma unroll
    for (int ii = 0; ii < 8; ii++) {
        const int row = by * 128 + (ty << 3) + ii;
#pragma unroll
        for (int jj = 0; jj < 4; jj++) {
            const int col = bx * 64 + (tx << 2) + jj;
            const float val = acc[ii][jj];
            const int h = (col >> 6) & 7, d = col & 63, w = col >> 9;
            if (w == 0)      g_q[(h * N_TOK + row) * DH + d] = val * 0.125f;
            else if (w == 1) g_k[(h * JPAD + row + 2) * DH + d] = val;
            else             g_v[(h * JPAD + row + 2) * DH + d] = val;
        }
    }
}

// ---------------- out projection GEMM (A = g_o + g_o2) ----------------
__global__ void gemm_proj(const float* __restrict__ B, float* __restrict__ C) {
    __shared__ float As[16][64];
    __shared__ float Bs[16][64];
    const int bx = blockIdx.x, by = blockIdx.y, tid = threadIdx.x;
    const int tx = tid & 15, ty = tid >> 4;
    const int ar = tid >> 2, ac = (tid & 3) << 2;
    const int br = tid >> 4, bc = (tid & 15) << 2;
    float acc[4][4] = {};

    const int aoff0 = (by * 64 + ar) * 512 + ac;
    float4 a4 = *(const float4*)(g_o + aoff0);
    float4 a4b = *(const float4*)(g_o2 + aoff0);
    a4.x += a4b.x; a4.y += a4b.y; a4.z += a4b.z; a4.w += a4b.w;
    float4 b4 = *(const float4*)(B + (size_t)br * 512 + bx * 64 + bc);

    for (int k0 = 0; k0 < 512; k0 += 16) {
        As[ac + 0][ar] = a4.x; As[ac + 1][ar] = a4.y;
        As[ac + 2][ar] = a4.z; As[ac + 3][ar] = a4.w;
        *(float4*)&Bs[br][bc] = b4;
        __syncthreads();
        if (k0 + 16 < 512) {
            const int aoff = (by * 64 + ar) * 512 + k0 + 16 + ac;
            a4 = *(const float4*)(g_o + aoff);
            a4b = *(const float4*)(g_o2 + aoff);
            a4.x += a4b.x; a4.y += a4b.y; a4.z += a4b.z; a4.w += a4b.w;
            b4 = *(const float4*)(B + (size_t)(k0 + 16 + br) * 512 + bx * 64 + bc);
        }
#pragma unroll
        for (int kk = 0; kk < 16; kk++) {
            float ra[4], rb[4];
            *(float4*)ra = *(const float4*)&As[kk][ty << 2];
            *(float4*)rb = *(const float4*)&Bs[kk][tx << 2];
#pragma unroll
            for (int ii = 0; ii < 4; ii++)
#pragma unroll
                for (int jj = 0; jj < 4; jj++)
                    acc[ii][jj] += ra[ii] * rb[jj];
        }
        __syncthreads();
    }
#pragma unroll
    for (int ii = 0; ii < 4; ii++) {
        const int row = by * 64 + (ty << 2) + ii;
#pragma unroll
        for (int jj = 0; jj < 4; jj++)
            C[row * 512 + bx * 64 + (tx << 2) + jj] = acc[ii][jj];
    }
}

// ---------------- sim = q . k^T: 128(i) x 64(j) tiles, d chunked by 32 ----------------
// Flat causal tile enumeration per head: for it2 in 0..7, jt in 0..2*it2+2 (80 tiles).
__global__ void sim_kernel() {
    const int f = blockIdx.x;         // 0..79
    const int h = blockIdx.y;
    int it2 = __float2int_rd(sqrtf((float)(f + 1))) - 1;
    while ((it2 + 1) * (it2 + 3) <= f) it2++;
    while (it2 * (it2 + 2) > f) it2--;
    const int jt = f - it2 * (it2 + 2);

    __shared__ float Qs[32][132];   // [d][i], 128 i
    __shared__ float Ks[32][68];    // [d][j], 64 j
    const int tid = threadIdx.x;
    const int tx = tid & 15, ty = tid >> 4;
    float acc[8][4] = {};

#pragma unroll
    for (int dc = 0; dc < 64; dc += 32) {
        // load Q: 128 rows x 32 d
        {
            const int row = tid >> 1;
            const int base = ((h << 10) + it2 * 128 + row) * DH + dc + ((tid & 1) << 4);
#pragma unroll
            for (int t = 0; t < 4; t++) {
                float4 q4 = *(const float4*)&g_q[base + t * 4];
                const int off = ((tid & 1) << 4) + t * 4;
                Qs[off + 0][row] = q4.x; Qs[off + 1][row] = q4.y;
                Qs[off + 2][row] = q4.z; Qs[off + 3][row] = q4.w;
            }
        }
        // load K: 64 rows x 32 d
        {
            const int row = tid >> 2;
            const int base = (h * JPAD + jt * 64 + row) * DH + dc + ((tid & 3) << 3);
#pragma unroll
            for (int t = 0; t < 2; t++) {
                float4 k4 = *(const float4*)&g_k[base + t * 4];
                const int off = ((tid & 3) << 3) + t * 4;
                Ks[off + 0][row] = k4.x; Ks[off + 1][row] = k4.y;
                Ks[off + 2][row] = k4.z; Ks[off + 3][row] = k4.w;
            }
        }
        __syncthreads();
#pragma unroll 8
        for (int d = 0; d < 32; d++) {
            float ra[8], rb[4];
            *(float4*)(ra)     = *(const float4*)&Qs[d][ty << 3];
            *(float4*)(ra + 4) = *(const float4*)&Qs[d][(ty << 3) + 4];
            *(float4*)rb       = *(const float4*)&Ks[d][tx << 2];
#pragma unroll
            for (int ii = 0; ii < 8; ii++)
#pragma unroll
                for (int jj = 0; jj < 4; jj++)
                    acc[ii][jj] += ra[ii] * rb[jj];
        }
        __syncthreads();
    }
#pragma unroll
    for (int ii = 0; ii < 8; ii++) {
        const int i = it2 * 128 + (ty << 3) + ii;
        float* srow = g_s + (size_t)(h * N_TOK + i) * JPAD;
        *(float4*)&srow[jt * 64 + (tx << 2)] =
            make_float4(acc[ii][0], acc[ii][1], acc[ii][2], acc[ii][3]);
    }
}

// ---------------- coordinate descent: one warp/row, size-bucketed templates ----------
template<int MAXU>
__device__ __forceinline__ void cd_row(float* __restrict__ srow, int lane, int jmax,
                                       int nchunk, int chunks) {
    float E1[MAXU];
    float tm = -3.4e38f;
#pragma unroll
    for (int u = 0; u < MAXU; u++) {
        E1[u] = -3.4e38f;
        if (u < nchunk) {
            const int j = lane + u * 32;
            if (j < jmax) { E1[u] = srow[j]; tm = fmaxf(tm, E1[u]); }
        }
    }
#pragma unroll
    for (int o = 16; o; o >>= 1) tm = fmaxf(tm, __shfl_xor_sync(0xffffffffu, tm, o));
    const float m = tm;
#pragma unroll
    for (int u = 0; u < MAXU; u++)
        if (u < nchunk)
            E1[u] = (E1[u] > -3.0e38f) ? __expf((E1[u] - m) * INV_EPS) : 0.0f;

    float a = EPSF * (LOGK - __logf((float)jmax));   // iter 1 closed form

    for (int it = 1; it < CD_ITERS; it++) {
        const float w = __expf((a + m) * INV_EPS);
        float ls0 = 0.0f, ls1 = 0.0f;
#pragma unroll
        for (int u = 0; u < MAXU; u++) {
            if (u < nchunk) {
                const float e = E1[u];
                const float c = fminf(e, w * (e * e));
                if (u & 1) ls1 += c; else ls0 += c;
            }
        }
        float ls = ls0 + ls1;
#pragma unroll
        for (int o = 16; o; o >>= 1) ls += __shfl_xor_sync(0xffffffffu, ls, o);
        const float a_new = EPSF * LOGK - m - EPSF * __logf(ls);
        const float da = fabsf(a_new - a);
        a = a_new;
        if (da < 5e-7f) break;
    }

    const float w = __expf((a + m) * INV_EPS);
#pragma unroll
    for (int u = 0; u < MAXU + 3; u++) {   // store only up to av's read limit
        if (u < chunks) {
            const int j = lane + u * 32;
            float val = 0.0f;
            if (u < MAXU && u < nchunk) {
                const float eu = w * E1[u];
                val = fminf(eu, eu * eu);
            }
            srow[j] = val;
        }
    }
}

__global__ void cd_kernel() {
    const int wg   = (blockIdx.x * blockDim.x + threadIdx.x) >> 5;  // 0..8191
    const int lane = threadIdx.x & 31;
    const int i = wg >> 3, h = wg & 7;       // adjacent warps share i -> uniform bucket
    const int jmax = i + 3;
    const int nchunk = (jmax + 31) >> 5;
    const int chunks = ((i >> 6) + 2) << 1;  // av reads j < 64*(i/64 + 2)
    float* srow = g_s + (size_t)(h * N_TOK + i) * JPAD;
    if (i < 254)      cd_row<8 >(srow, lane, jmax, nchunk, chunks);
    else if (i < 510) cd_row<16>(srow, lane, jmax, nchunk, chunks);
    else if (i < 766) cd_row<24>(srow, lane, jmax, nchunk, chunks);
    else              cd_row<33>(srow, lane, jmax, nchunk, chunks);
}

// ---------------- out = attn . v : split-K over j, partials to g_o / g_o2 ------------
__global__ void av_kernel() {
    const int it = blockIdx.x;
    const int h  = blockIdx.y;
    const int sp = blockIdx.z;
    const int T = it + 2;
    const int half = T >> 1;
    const int j0 = sp ? half : 0;
    const int j1 = sp ? T : half;
    __shared__ float Ps[64][65];
    __shared__ float Vs[64][64];
    const int tid = threadIdx.x;
    const int tx = tid & 15, ty = tid >> 4;
    const int c = (tid & 15) << 2;
    float acc[4][4] = {};
    for (int jt = j0; jt < j1; jt++) {
#pragma unroll
        for (int t = 0; t < 4; t++) {
            const int r = (tid >> 4) + t * 16;
            float4 p4 = *(const float4*)&g_s[(size_t)(h * N_TOK + it * 64 + r) * JPAD + jt * 64 + c];
            Ps[c + 0][r] = p4.x; Ps[c + 1][r] = p4.y; Ps[c + 2][r] = p4.z; Ps[c + 3][r] = p4.w;
            float4 v4 = *(const float4*)&g_v[(h * JPAD + jt * 64 + r) * DH + c];
            *(float4*)&Vs[r][c] = v4;
        }
        __syncthreads();
#pragma unroll 16
        for (int j = 0; j < 64; j++) {
            float ra[4], rb[4];
#pragma unroll
            for (int ii = 0; ii < 4; ii++) ra[ii] = Ps[j][(ty << 2) + ii];
#pragma unroll
            for (int jj = 0; jj < 4; jj++) rb[jj] = Vs[j][(tx << 2) + jj];
#pragma unroll
            for (int ii = 0; ii < 4; ii++)
#pragma unroll
                for (int jj = 0; jj < 4; jj++)
                    acc[ii][jj] += ra[ii] * rb[jj];
        }
        __syncthreads();
    }
    float* outp = sp ? g_o2 : g_o;
#pragma unroll
    for (int ii = 0; ii < 4; ii++) {
        const int row = it * 64 + (ty << 2) + ii;
#pragma unroll
        for (int jj = 0; jj < 4; jj++)
            outp[row * DIMV + h * DH + (tx << 2) + jj] = acc[ii][jj];
    }
}

// ---------------- launch ----------------
extern "C" void kernel_launch(void* const* d_in, const int* in_sizes, int n_in,
                              void* d_out, int out_size) {
    const float* x       = (const float*)d_in[0];
    const float* w_qkv   = (const float*)d_in[1];
    const float* w_out   = (const float*)d_in[2];
    const float* null_kv = (const float*)d_in[3];
    const float* ln_g    = (const float*)d_in[4];
    const float* ln_b    = (const float*)d_in[5];
    float* out = (float*)d_out;

    ln_fill_kernel<<<1152, 256>>>(x, ln_g, ln_b, null_kv);
    gemm_qkv   <<<dim3(24, 8), 256>>>(w_qkv);
    sim_kernel <<<dim3(80, HEADS), 256>>>();
    cd_kernel  <<<2048, 128>>>();
    av_kernel  <<<dim3(16, HEADS, 2), 256>>>();
    gemm_proj  <<<dim3(8, 16), 256>>>(w_out, out);
}

// round 7
// speedup vs baseline: 3.6993x; 1.0090x over previous
#include <cuda_runtime.h>
#include <math.h>
#include <stdint.h>

#define N_TOK 1024
#define DIMV  512
#define HEADS 8
#define DH    64
#define JTOT  1026
#define JPAD  1088          // 17 * 64 = 34 * 32
#define INV_EPS 10.0f
#define EPSF    0.1f
#define LOGK    2.0794415416798357f   // log(8)
#define CD_ITERS 50

// ---------------- scratch ----------------
__device__ float g_xn[N_TOK * DIMV];
__device__ float g_q [HEADS * N_TOK * DH];
__device__ float g_k [HEADS * JPAD * DH];
__device__ float g_v [HEADS * JPAD * DH];
__device__ float g_s [HEADS * N_TOK * JPAD];
__device__ float g_o [N_TOK * DIMV];
__device__ float g_o2[N_TOK * DIMV];

// ---------------- packed f32x2 helpers ----------------
__device__ __forceinline__ void ffma2(uint64_t& acc, uint64_t a, uint64_t b) {
    asm("fma.rn.f32x2 %0, %1, %2, %0;" : "+l"(acc) : "l"(a), "l"(b));
}
__device__ __forceinline__ uint64_t bcast2(float v) {
    uint64_t r;
    const uint32_t u = __float_as_uint(v);
    asm("mov.b64 %0, {%1, %1};" : "=l"(r) : "r"(u));
    return r;
}
__device__ __forceinline__ float lo32(uint64_t v) { return __uint_as_float((uint32_t)v); }
__device__ __forceinline__ float hi32(uint64_t v) { return __uint_as_float((uint32_t)(v >> 32)); }

// ---------------- block reduction ----------------
__device__ __forceinline__ float block_sum_256(float v, float* red) {
#pragma unroll
    for (int o = 16; o; o >>= 1) v += __shfl_xor_sync(0xffffffffu, v, o);
    __syncthreads();
    if ((threadIdx.x & 31) == 0) red[threadIdx.x >> 5] = v;
    __syncthreads();
    v = red[threadIdx.x & 7];
#pragma unroll
    for (int o = 4; o; o >>= 1) v += __shfl_xor_sync(0xffffffffu, v, o);
    return v;
}

// ---------------- fused LayerNorm + null-kv/pad fill ----------------
__global__ void ln_fill_kernel(const float* __restrict__ x, const float* __restrict__ gam,
                               const float* __restrict__ bet,
                               const float* __restrict__ null_kv) {
    if (blockIdx.x >= 1024) {
        const int idx = (blockIdx.x - 1024) * 256 + threadIdx.x;
        const int h = idx >> 12;
        const int r = (idx >> 6) & 63;
        const int d = idx & 63;
        if (r < 2) {
            g_k[(h * JPAD + r) * DH + d] = null_kv[((0 * HEADS + h) * 2 + r) * DH + d];
            g_v[(h * JPAD + r) * DH + d] = null_kv[((1 * HEADS + h) * 2 + r) * DH + d];
        } else {
            const int j = 1024 + r;
            g_k[(h * JPAD + j) * DH + d] = 0.0f;
            g_v[(h * JPAD + j) * DH + d] = 0.0f;
        }
        return;
    }
    __shared__ float red[8];
    const int row = blockIdx.x;
    const int tid = threadIdx.x;
    const float v0 = x[row * DIMV + tid];
    const float v1 = x[row * DIMV + tid + 256];
    float s  = v0 + v1;
    float sq = v0 * v0 + v1 * v1;
    s  = block_sum_256(s,  red);
    sq = block_sum_256(sq, red);
    const float mean = s * (1.0f / 512.0f);
    const float var  = sq * (1.0f / 512.0f) - mean * mean;
    const float rstd = rsqrtf(var + 1e-5f);
    g_xn[row * DIMV + tid]       = (v0 - mean) * rstd * gam[tid]       + bet[tid];
    g_xn[row * DIMV + tid + 256] = (v1 - mean) * rstd * gam[tid + 256] + bet[tid + 256];
}

// ---------------- QKV GEMM: 128x64 tile, 8x4 micro via f32x2 pairs --------------------
__global__ void gemm_qkv(const float* __restrict__ B) {
    __shared__ __align__(16) float As[16][132];
    __shared__ __align__(16) float Bs[16][64];
    const float* __restrict__ A = g_xn;
    const int bx = blockIdx.x, by = blockIdx.y, tid = threadIdx.x;
    const int tx = tid & 15, ty = tid >> 4;
    const int ar = tid >> 2, ac = (tid & 3) << 2;
    const int br = tid >> 4, bc = (tid & 15) << 2;
    uint64_t acc2[4][4] = {};   // 4 row-pairs x 4 cols

    float4 a0 = *(const float4*)(A + (by * 128 + ar) * 512 + ac);
    float4 a1 = *(const float4*)(A + (by * 128 + ar + 64) * 512 + ac);
    float4 b0 = *(const float4*)(B + (size_t)br * 1536 + bx * 64 + bc);

    for (int k0 = 0; k0 < 512; k0 += 16) {
        As[ac + 0][ar] = a0.x; As[ac + 1][ar] = a0.y;
        As[ac + 2][ar] = a0.z; As[ac + 3][ar] = a0.w;
        As[ac + 0][ar + 64] = a1.x; As[ac + 1][ar + 64] = a1.y;
        As[ac + 2][ar + 64] = a1.z; As[ac + 3][ar + 64] = a1.w;
        *(float4*)&Bs[br][bc] = b0;
        __syncthreads();
        if (k0 + 16 < 512) {
            a0 = *(const float4*)(A + (by * 128 + ar) * 512 + k0 + 16 + ac);
            a1 = *(const float4*)(A + (by * 128 + ar + 64) * 512 + k0 + 16 + ac);
            b0 = *(const float4*)(B + (size_t)(k0 + 16 + br) * 1536 + bx * 64 + bc);
        }
#pragma unroll
        for (int kk = 0; kk < 16; kk++) {
            const uint64_t* ap = (const uint64_t*)&As[kk][ty << 3];
            uint64_t ra[4];
            ra[0] = ap[0]; ra[1] = ap[1]; ra[2] = ap[2]; ra[3] = ap[3];
            float4 bq = *(const float4*)&Bs[kk][tx << 2];
            uint64_t rb[4];
            rb[0] = bcast2(bq.x); rb[1] = bcast2(bq.y);
            rb[2] = bcast2(bq.z); rb[3] = bcast2(bq.w);
#pragma unroll
            for (int p = 0; p < 4; p++)
#pragma unroll
                for (int j = 0; j < 4; j++)
                    ffma2(acc2[p][j], ra[p], rb[j]);
        }
        __syncthreads();
    }
#pragma unroll
    for (int p = 0; p < 4; p++) {
#pragma unroll
        for (int j = 0; j < 4; j++) {
            const int col = bx * 64 + (tx << 2) + j;
            const int h = (col >> 6) & 7, d = col & 63, w = col >> 9;
            const int row0 = by * 128 + (ty << 3) + 2 * p;
            const float vlo = lo32(acc2[p][j]);
            const float vhi = hi32(acc2[p][j]);
            if (w == 0) {
                g_q[(h * N_TOK + row0) * DH + d]     = vlo * 0.125f;
                g_q[(h * N_TOK + row0 + 1) * DH + d] = vhi * 0.125f;
            } else if (w == 1) {
                g_k[(h * JPAD + row0 + 2) * DH + d] = vlo;
                g_k[(h * JPAD + row0 + 3) * DH + d] = vhi;
            } else {
                g_v[(h * JPAD + row0 + 2) * DH + d] = vlo;
                g_v[(h * JPAD + row0 + 3) * DH + d] = vhi;
            }
        }
    }
}

// ---------------- out projection GEMM: 64x64 tile, f32x2 pairs ------------------------
__global__ void gemm_proj(const float* __restrict__ B, float* __restrict__ C) {
    __shared__ __align__(16) float As[16][64];
    __shared__ __align__(16) float Bs[16][64];
    const int bx = blockIdx.x, by = blockIdx.y, tid = threadIdx.x;
    const int tx = tid & 15, ty = tid >> 4;
    const int ar = tid >> 2, ac = (tid & 3) << 2;
    const int br = tid >> 4, bc = (tid & 15) << 2;
    uint64_t acc2[2][4] = {};   // 2 row-pairs x 4 cols

    const int aoff0 = (by * 64 + ar) * 512 + ac;
    float4 a4 = *(const float4*)(g_o + aoff0);
    float4 a4b = *(const float4*)(g_o2 + aoff0);
    a4.x += a4b.x; a4.y += a4b.y; a4.z += a4b.z; a4.w += a4b.w;
    float4 b4 = *(const float4*)(B + (size_t)br * 512 + bx * 64 + bc);

    for (int k0 = 0; k0 < 512; k0 += 16) {
        As[ac + 0][ar] = a4.x; As[ac + 1][ar] = a4.y;
        As[ac + 2][ar] = a4.z; As[ac + 3][ar] = a4.w;
        *(float4*)&Bs[br][bc] = b4;
        __syncthreads();
        if (k0 + 16 < 512) {
            const int aoff = (by * 64 + ar) * 512 + k0 + 16 + ac;
            a4 = *(const float4*)(g_o + aoff);
            a4b = *(const float4*)(g_o2 + aoff);
            a4.x += a4b.x; a4.y += a4b.y; a4.z += a4b.z; a4.w += a4b.w;
            b4 = *(const float4*)(B + (size_t)(k0 + 16 + br) * 512 + bx * 64 + bc);
        }
#pragma unroll
        for (int kk = 0; kk < 16; kk++) {
            const uint64_t* ap = (const uint64_t*)&As[kk][ty << 2];
            uint64_t ra[2];
            ra[0] = ap[0]; ra[1] = ap[1];
            float4 bq = *(const float4*)&Bs[kk][tx << 2];
            uint64_t rb[4];
            rb[0] = bcast2(bq.x); rb[1] = bcast2(bq.y);
            rb[2] = bcast2(bq.z); rb[3] = bcast2(bq.w);
#pragma unroll
            for (int p = 0; p < 2; p++)
#pragma unroll
                for (int j = 0; j < 4; j++)
                    ffma2(acc2[p][j], ra[p], rb[j]);
        }
        __syncthreads();
    }
#pragma unroll
    for (int p = 0; p < 2; p++) {
        const int row0 = by * 64 + (ty << 2) + 2 * p;
        const int colb = bx * 64 + (tx << 2);
        C[row0 * 512 + colb + 0] = lo32(acc2[p][0]);
        C[row0 * 512 + colb + 1] = lo32(acc2[p][1]);
        C[row0 * 512 + colb + 2] = lo32(acc2[p][2]);
        C[row0 * 512 + colb + 3] = lo32(acc2[p][3]);
        C[(row0 + 1) * 512 + colb + 0] = hi32(acc2[p][0]);
        C[(row0 + 1) * 512 + colb + 1] = hi32(acc2[p][1]);
        C[(row0 + 1) * 512 + colb + 2] = hi32(acc2[p][2]);
        C[(row0 + 1) * 512 + colb + 3] = hi32(acc2[p][3]);
    }
}

// ---------------- sim = q . k^T: 128(i) x 64(j) tiles, f32x2 pairs --------------------
__global__ void sim_kernel() {
    const int f = blockIdx.x;
    const int h = blockIdx.y;
    int it2 = __float2int_rd(sqrtf((float)(f + 1))) - 1;
    while ((it2 + 1) * (it2 + 3) <= f) it2++;
    while (it2 * (it2 + 2) > f) it2--;
    const int jt = f - it2 * (it2 + 2);

    __shared__ __align__(16) float Qs[32][132];
    __shared__ __align__(16) float Ks[32][68];
    const int tid = threadIdx.x;
    const int tx = tid & 15, ty = tid >> 4;
    uint64_t acc2[4][4] = {};   // 4 i-pairs x 4 j

#pragma unroll
    for (int dc = 0; dc < 64; dc += 32) {
        {
            const int row = tid >> 1;
            const int base = ((h << 10) + it2 * 128 + row) * DH + dc + ((tid & 1) << 4);
#pragma unroll
            for (int t = 0; t < 4; t++) {
                float4 q4 = *(const float4*)&g_q[base + t * 4];
                const int off = ((tid & 1) << 4) + t * 4;
                Qs[off + 0][row] = q4.x; Qs[off + 1][row] = q4.y;
                Qs[off + 2][row] = q4.z; Qs[off + 3][row] = q4.w;
            }
        }
        {
            const int row = tid >> 2;
            const int base = (h * JPAD + jt * 64 + row) * DH + dc + ((tid & 3) << 3);
#pragma unroll
            for (int t = 0; t < 2; t++) {
                float4 k4 = *(const float4*)&g_k[base + t * 4];
                const int off = ((tid & 3) << 3) + t * 4;
                Ks[off + 0][row] = k4.x; Ks[off + 1][row] = k4.y;
                Ks[off + 2][row] = k4.z; Ks[off + 3][row] = k4.w;
            }
        }
        __syncthreads();
#pragma unroll 8
        for (int d = 0; d < 32; d++) {
            const uint64_t* ap = (const uint64_t*)&Qs[d][ty << 3];
            uint64_t ra[4];
            ra[0] = ap[0]; ra[1] = ap[1]; ra[2] = ap[2]; ra[3] = ap[3];
            float4 kq = *(const float4*)&Ks[d][tx << 2];
            uint64_t rb[4];
            rb[0] = bcast2(kq.x); rb[1] = bcast2(kq.y);
            rb[2] = bcast2(kq.z); rb[3] = bcast2(kq.w);
#pragma unroll
            for (int p = 0; p < 4; p++)
#pragma unroll
                for (int j = 0; j < 4; j++)
                    ffma2(acc2[p][j], ra[p], rb[j]);
        }
        __syncthreads();
    }
#pragma unroll
    for (int p = 0; p < 4; p++) {
        const int i0 = it2 * 128 + (ty << 3) + 2 * p;
        float* sr0 = g_s + (size_t)(h * N_TOK + i0) * JPAD + jt * 64 + (tx << 2);
        float* sr1 = sr0 + JPAD;
        *(float4*)sr0 = make_float4(lo32(acc2[p][0]), lo32(acc2[p][1]),
                                    lo32(acc2[p][2]), lo32(acc2[p][3]));
        *(float4*)sr1 = make_float4(hi32(acc2[p][0]), hi32(acc2[p][1]),
                                    hi32(acc2[p][2]), hi32(acc2[p][3]));
    }
}

// ---------------- coordinate descent (unchanged round-5) ----------------
template<int MAXU>
__device__ __forceinline__ void cd_row(float* __restrict__ srow, int lane, int jmax,
                                       int nchunk, int chunks) {
    float E1[MAXU];
    float tm = -3.4e38f;
#pragma unroll
    for (int u = 0; u < MAXU; u++) {
        E1[u] = -3.4e38f;
        if (u < nchunk) {
            const int j = lane + u * 32;
            if (j < jmax) { E1[u] = srow[j]; tm = fmaxf(tm, E1[u]); }
        }
    }
#pragma unroll
    for (int o = 16; o; o >>= 1) tm = fmaxf(tm, __shfl_xor_sync(0xffffffffu, tm, o));
    const float m = tm;
#pragma unroll
    for (int u = 0; u < MAXU; u++)
        if (u < nchunk)
            E1[u] = (E1[u] > -3.0e38f) ? __expf((E1[u] - m) * INV_EPS) : 0.0f;

    float a = EPSF * (LOGK - __logf((float)jmax));

    for (int it = 1; it < CD_ITERS; it++) {
        const float w = __expf((a + m) * INV_EPS);
        float ls0 = 0.0f, ls1 = 0.0f;
#pragma unroll
        for (int u = 0; u < MAXU; u++) {
            if (u < nchunk) {
                const float e = E1[u];
                const float c = fminf(e, w * (e * e));
                if (u & 1) ls1 += c; else ls0 += c;
            }
        }
        float ls = ls0 + ls1;
#pragma unroll
        for (int o = 16; o; o >>= 1) ls += __shfl_xor_sync(0xffffffffu, ls, o);
        const float a_new = EPSF * LOGK - m - EPSF * __logf(ls);
        const float da = fabsf(a_new - a);
        a = a_new;
        if (da < 5e-7f) break;
    }

    const float w = __expf((a + m) * INV_EPS);
#pragma unroll
    for (int u = 0; u < MAXU + 3; u++) {
        if (u < chunks) {
            const int j = lane + u * 32;
            float val = 0.0f;
            if (u < MAXU && u < nchunk) {
                const float eu = w * E1[u];
                val = fminf(eu, eu * eu);
            }
            srow[j] = val;
        }
    }
}

__global__ void cd_kernel() {
    const int wg   = (blockIdx.x * blockDim.x + threadIdx.x) >> 5;
    const int lane = threadIdx.x & 31;
    const int i = wg >> 3, h = wg & 7;
    const int jmax = i + 3;
    const int nchunk = (jmax + 31) >> 5;
    const int chunks = ((i >> 6) + 2) << 1;
    float* srow = g_s + (size_t)(h * N_TOK + i) * JPAD;
    if (i < 254)      cd_row<8 >(srow, lane, jmax, nchunk, chunks);
    else if (i < 510) cd_row<16>(srow, lane, jmax, nchunk, chunks);
    else if (i < 766) cd_row<24>(srow, lane, jmax, nchunk, chunks);
    else              cd_row<33>(srow, lane, jmax, nchunk, chunks);
}

// ---------------- out = attn . v : split-K over j, f32x2 pairs ------------------------
__global__ void av_kernel() {
    const int it = blockIdx.x;
    const int h  = blockIdx.y;
    const int sp = blockIdx.z;
    const int T = it + 2;
    const int half = T >> 1;
    const int j0 = sp ? half : 0;
    const int j1 = sp ? T : half;
    __shared__ __align__(16) float Ps[64][66];
    __shared__ __align__(16) float Vs[64][64];
    const int tid = threadIdx.x;
    const int tx = tid & 15, ty = tid >> 4;
    const int c = (tid & 15) << 2;
    uint64_t acc2[2][4] = {};   // 2 i-pairs x 4 d
    for (int jt = j0; jt < j1; jt++) {
#pragma unroll
        for (int t = 0; t < 4; t++) {
            const int r = (tid >> 4) + t * 16;
            float4 p4 = *(const float4*)&g_s[(size_t)(h * N_TOK + it * 64 + r) * JPAD + jt * 64 + c];
            Ps[c + 0][r] = p4.x; Ps[c + 1][r] = p4.y; Ps[c + 2][r] = p4.z; Ps[c + 3][r] = p4.w;
            float4 v4 = *(const float4*)&g_v[(h * JPAD + jt * 64 + r) * DH + c];
            *(float4*)&Vs[r][c] = v4;
        }
        __syncthreads();
#pragma unroll 16
        for (int j = 0; j < 64; j++) {
            const uint64_t* ap = (const uint64_t*)&Ps[j][ty << 2];
            uint64_t ra[2];
            ra[0] = ap[0]; ra[1] = ap[1];
            float4 vq = *(const float4*)&Vs[j][tx << 2];
            uint64_t rb[4];
            rb[0] = bcast2(vq.x); rb[1] = bcast2(vq.y);
            rb[2] = bcast2(vq.z); rb[3] = bcast2(vq.w);
#pragma unroll
            for (int p = 0; p < 2; p++)
#pragma unroll
                for (int jj = 0; jj < 4; jj++)
                    ffma2(acc2[p][jj], ra[p], rb[jj]);
        }
        __syncthreads();
    }
    float* outp = sp ? g_o2 : g_o;
#pragma unroll
    for (int p = 0; p < 2; p++) {
        const int row0 = it * 64 + (ty << 2) + 2 * p;
        float* o0 = outp + row0 * DIMV + h * DH + (tx << 2);
        float* o1 = o0 + DIMV;
        *(float4*)o0 = make_float4(lo32(acc2[p][0]), lo32(acc2[p][1]),
                                   lo32(acc2[p][2]), lo32(acc2[p][3]));
        *(float4*)o1 = make_float4(hi32(acc2[p][0]), hi32(acc2[p][1]),
                                   hi32(acc2[p][2]), hi32(acc2[p][3]));
    }
}

// ---------------- launch ----------------
extern "C" void kernel_launch(void* const* d_in, const int* in_sizes, int n_in,
                              void* d_out, int out_size) {
    const float* x       = (const float*)d_in[0];
    const float* w_qkv   = (const float*)d_in[1];
    const float* w_out   = (const float*)d_in[2];
    const float* null_kv = (const float*)d_in[3];
    const float* ln_g    = (const float*)d_in[4];
    const float* ln_b    = (const float*)d_in[5];
    float* out = (float*)d_out;

    ln_fill_kernel<<<1152, 256>>>(x, ln_g, ln_b, null_kv);
    gemm_qkv   <<<dim3(24, 8), 256>>>(w_qkv);
    sim_kernel <<<dim3(80, HEADS), 256>>>();
    cd_kernel  <<<2048, 128>>>();
    av_kernel  <<<dim3(16, HEADS, 2), 256>>>();
    gemm_proj  <<<dim3(8, 16), 256>>>(w_out, out);
}